// round 8
// baseline (speedup 1.0000x reference)
#include <cuda_runtime.h>
#include <cstdint>

#define BS 32
#define NN 1024
#define FO 128
#define NWORDS 32

#define RW 4                   // rows per warp
#define BW 2                   // batches per block/warp
#define WARPS 8
#define ROWS_PER_BLOCK 32      // RW * WARPS
#define PACK_BLOCKS 512

// Scratch (__device__ globals; no allocations allowed)
__device__ uint32_t g_adjw[NN * NWORDS];   // 128 KB packed adjacency
__device__ float4   g_pre[BS * NN];        // {s2, s1, e2, e2*x}  512 KB
__device__ float    g_meanx[BS];

// ---------------------------------------------------------------------------
// Setup: (a) pack adj via 2x LDG.128/thread + shfl byte-pack,
//        (b) per-batch: c1,c2 (local reduction), mean(x), and g_pre fill.
// ---------------------------------------------------------------------------
__global__ void __launch_bounds__(256) k_setup(const int* __restrict__ adj,
                                               const float* __restrict__ x,
                                               const float* __restrict__ W,
                                               const float* __restrict__ a) {
    int bid = blockIdx.x;
    int tid = threadIdx.x;

    if (bid < PACK_BLOCKS) {
        int t = bid * 256 + tid;
        const int4* a4 = reinterpret_cast<const int4*>(adj);
        int4 v0 = a4[2 * t];
        int4 v1 = a4[2 * t + 1];
        uint32_t m = 0;
        m |= (v0.x > 0) ? 1u   : 0u;
        m |= (v0.y > 0) ? 2u   : 0u;
        m |= (v0.z > 0) ? 4u   : 0u;
        m |= (v0.w > 0) ? 8u   : 0u;
        m |= (v1.x > 0) ? 16u  : 0u;
        m |= (v1.y > 0) ? 32u  : 0u;
        m |= (v1.z > 0) ? 64u  : 0u;
        m |= (v1.w > 0) ? 128u : 0u;
        int lane = tid & 31;
        uint32_t val = m << ((lane & 3) * 8);
        val |= __shfl_xor_sync(0xffffffffu, val, 1);
        val |= __shfl_xor_sync(0xffffffffu, val, 2);
        uint32_t w = __shfl_sync(0xffffffffu, val, (lane & 7) * 4);
        int wbase = (t >> 5) * 8;
        if (lane < 8) g_adjw[wbase + lane] = w;
        return;
    }

    // One block per batch: scalars + mean + precompute
    int b = bid - PACK_BLOCKS;
    __shared__ float red[256];
    __shared__ float s_c1, s_c2;

    float p = (tid < FO) ? W[tid] * a[tid] : 0.f;
    red[tid] = p; __syncthreads();
    for (int st = 128; st > 0; st >>= 1) {
        if (tid < st) red[tid] += red[tid + st];
        __syncthreads();
    }
    if (tid == 0) s_c1 = red[0];
    __syncthreads();

    p = (tid < FO) ? W[tid] * a[FO + tid] : 0.f;
    red[tid] = p; __syncthreads();
    for (int st = 128; st > 0; st >>= 1) {
        if (tid < st) red[tid] += red[tid + st];
        __syncthreads();
    }
    if (tid == 0) s_c2 = red[0];
    __syncthreads();

    float s = 0.f;
    for (int n = tid; n < NN; n += 256) s += x[(size_t)b * NN + n];
    red[tid] = s; __syncthreads();
    for (int st = 128; st > 0; st >>= 1) {
        if (tid < st) red[tid] += red[tid + st];
        __syncthreads();
    }
    if (tid == 0) g_meanx[b] = red[0] * (1.0f / NN);

    float c1 = s_c1, c2 = s_c2;
    for (int n = tid; n < NN; n += 256) {
        float xv = x[(size_t)b * NN + n];
        float s2 = c2 * xv;
        float s1 = c1 * xv;
        float e2 = __expf(s2);
        g_pre[(size_t)b * NN + n] = make_float4(s2, s1, e2, e2 * xv);
    }
}

// ---------------------------------------------------------------------------
// Main: grid (32, 16), 256 threads. Warp = 4 rows x 2 batches.
// Inner loop: LDS.128 adj (4 rows) + per-b LDS.128 pre + per-pair
// FSETP.AND + 2 predicated FADDs. No exp/mul in the loop.
// Keep-predicate identical: bit && (s2_j > -s1_i).
// ---------------------------------------------------------------------------
__device__ __forceinline__ float elu_fast(float v) {
    return v > 0.f ? v : (__expf(v) - 1.0f);
}

__global__ void __launch_bounds__(256, 4) k_main(const float* __restrict__ W,
                                                 float* __restrict__ out) {
    __shared__ float4   s_pre[BW][NN];                   // 32 KB
    __shared__ uint32_t s_adjT[NWORDS][ROWS_PER_BLOCK];  // 4 KB
    __shared__ float    s_W[FO];                         // 512 B

    int tid  = threadIdx.x;
    int lane = tid & 31;
    int warp = tid >> 5;
    int row0 = blockIdx.x * ROWS_PER_BLOCK;
    int b0   = blockIdx.y * BW;

    // cooperative loads
    {
        const float4* src = &g_pre[(size_t)b0 * NN];
        float4* dst = &s_pre[0][0];
        for (int t = tid; t < BW * NN; t += 256) dst[t] = src[t];
    }
    for (int t = tid; t < ROWS_PER_BLOCK * NWORDS; t += 256) {
        int r = t >> 5, kk = t & 31;
        s_adjT[kk][r] = g_adjw[(row0 + r) * NWORDS + kk];
    }
    if (tid < FO) s_W[tid] = W[tid];
    __syncthreads();

    const int ir = warp * RW;
    const uint32_t lanebit = 1u << lane;

    float thr[RW][BW], den[RW][BW], num[RW][BW];
#pragma unroll
    for (int r = 0; r < RW; r++)
#pragma unroll
        for (int b = 0; b < BW; b++) {
            thr[r][b] = -s_pre[b][row0 + ir + r].y;   // -s1_i
            den[r][b] = 0.f;
            num[r][b] = 0.f;
        }

#pragma unroll 4
    for (int kk = 0; kk < NWORDS; kk++) {
        uint4 w = *reinterpret_cast<const uint4*>(&s_adjT[kk][ir]);  // LDS.128
        bool p0 = (w.x & lanebit) != 0;
        bool p1 = (w.y & lanebit) != 0;
        bool p2 = (w.z & lanebit) != 0;
        bool p3 = (w.w & lanebit) != 0;
#pragma unroll
        for (int b = 0; b < BW; b++) {
            float4 q = s_pre[b][kk * 32 + lane];   // {s2, s1, e2, e2x}
            if (p0 && (q.x > thr[0][b])) { den[0][b] += q.z; num[0][b] += q.w; }
            if (p1 && (q.x > thr[1][b])) { den[1][b] += q.z; num[1][b] += q.w; }
            if (p2 && (q.x > thr[2][b])) { den[2][b] += q.z; num[2][b] += q.w; }
            if (p3 && (q.x > thr[3][b])) { den[3][b] += q.z; num[3][b] += q.w; }
        }
    }

    float meanx[BW];
#pragma unroll
    for (int b = 0; b < BW; b++) meanx[b] = g_meanx[b0 + b];

    const float4 wv = reinterpret_cast<const float4*>(s_W)[lane];

#pragma unroll
    for (int r = 0; r < RW; r++) {
        int i = row0 + ir + r;
#pragma unroll
        for (int b = 0; b < BW; b++) {
            float d = den[r][b], nm = num[r][b];
#pragma unroll
            for (int o = 16; o > 0; o >>= 1) {
                d  += __shfl_xor_sync(0xffffffffu, d,  o);
                nm += __shfl_xor_sync(0xffffffffu, nm, o);
            }
            float y = (d > 0.f) ? (nm / d) : meanx[b];
            float4 z;
            z.x = elu_fast(y * wv.x);
            z.y = elu_fast(y * wv.y);
            z.z = elu_fast(y * wv.z);
            z.w = elu_fast(y * wv.w);
            reinterpret_cast<float4*>(out)[((size_t)(b0 + b) * NN + i) * (FO / 4) + lane] = z;
        }
    }
}

// ---------------------------------------------------------------------------
// Inputs per metadata order: input, adj, ext_input, side_input, W, a
// ---------------------------------------------------------------------------
extern "C" void kernel_launch(void* const* d_in, const int* in_sizes, int n_in,
                              void* d_out, int out_size) {
    const float* input = (const float*)d_in[0];
    const int*   adj   = (const int*)  d_in[1];
    const float* W     = (const float*)d_in[4];
    const float* a     = (const float*)d_in[5];
    float* out = (float*)d_out;

    k_setup<<<PACK_BLOCKS + BS, 256>>>(adj, input, W, a);
    k_main<<<dim3(NN / ROWS_PER_BLOCK, BS / BW), 256>>>(W, out);
}